// round 2
// baseline (speedup 1.0000x reference)
#include <cuda_runtime.h>
#include <math.h>

// ---------------------------------------------------------------------------
// Problem dims (fixed by the dataset)
// ---------------------------------------------------------------------------
#define Bn 8
#define H 64
#define W 128
#define HW (H * W)            // 8192
#define C1CH 96               // tenOne / tenTwo channels
#define HIN 32
#define WIN 64
#define HWIN (HIN * WIN)      // 2048
#define PREVC 661

#define FEAT_C 629
#define FEAT_STRIDE (FEAT_C * HW)   // per-batch stride of feat, 5152768

// channel offsets inside final feat (concats prepend):
// [c5(32) | c4(64) | c3(96) | c2(128) | c1(128) | vol(81) | tenOne(96) | flow(2) | upfeat(2)]
#define OFF_C5   0
#define OFF_C4   32
#define OFF_C3   96
#define OFF_C2   192
#define OFF_C1   320
#define OFF_VOL  448
#define OFF_T1   529
#define OFF_FLOW 625
#define OFF_UPF  627

// scratch: warped tenTwo
__device__ float g_warped[(size_t)Bn * C1CH * HW];

// ---------------------------------------------------------------------------
// ConvTranspose2d(k=4, s=2, p=1), Cout = 2.  out[o] += in[i]*w[k], o = 2i-1+k.
// For each output coord there are exactly 2 (i,k) pairs per axis.
// Weight layout: (Cin, 2, 4, 4).
// ---------------------------------------------------------------------------
__global__ void upconv_kernel(const float* __restrict__ in,
                              const float* __restrict__ w,
                              const float* __restrict__ bias,
                              float* __restrict__ out,   // feat slice, batch-0 channel ptr
                              int Cin)
{
    int gid = blockIdx.x * blockDim.x + threadIdx.x;
    if (gid >= Bn * HW) return;
    int b = gid / HW;
    int pix = gid - b * HW;
    int y = pix / W, x = pix - (pix / W) * W;

    int iy0 = y >> 1,                      ky0 = 1 + (y & 1);
    int iy1 = (y >> 1) + ((y & 1) ? 1 : -1), ky1 = (y & 1) ? 0 : 3;
    int ix0 = x >> 1,                      kx0 = 1 + (x & 1);
    int ix1 = (x >> 1) + ((x & 1) ? 1 : -1), kx1 = (x & 1) ? 0 : 3;
    bool vy1 = (unsigned)iy1 < HIN;
    bool vx1 = (unsigned)ix1 < WIN;

    float a0 = bias[0], a1 = bias[1];
    const float* pin = in + (size_t)b * Cin * HWIN;
    int w00i = ky0 * 4 + kx0, w01i = ky0 * 4 + kx1;
    int w10i = ky1 * 4 + kx0, w11i = ky1 * 4 + kx1;
    int p00 = iy0 * WIN + ix0, p01 = iy0 * WIN + ix1;
    int p10 = iy1 * WIN + ix0, p11 = iy1 * WIN + ix1;

    for (int ci = 0; ci < Cin; ci++) {
        const float* p = pin + (size_t)ci * HWIN;
        const float* wc = w + (size_t)ci * 32;
        float v = p[p00];
        a0 += v * wc[w00i];       a1 += v * wc[16 + w00i];
        if (vx1)        { float u = p[p01]; a0 += u * wc[w01i]; a1 += u * wc[16 + w01i]; }
        if (vy1)        { float u = p[p10]; a0 += u * wc[w10i]; a1 += u * wc[16 + w10i]; }
        if (vy1 && vx1) { float u = p[p11]; a0 += u * wc[w11i]; a1 += u * wc[16 + w11i]; }
    }
    out[(size_t)b * FEAT_STRIDE + pix]      = a0;
    out[(size_t)b * FEAT_STRIDE + HW + pix] = a1;
}

// ---------------------------------------------------------------------------
// Copy tenOne into its feat slice (float4 vectorized; batches contiguous)
// ---------------------------------------------------------------------------
__global__ void copy_t1_kernel(const float* __restrict__ t1, float* __restrict__ feat)
{
    size_t i = (size_t)blockIdx.x * blockDim.x + threadIdx.x;
    const size_t n4 = (size_t)Bn * C1CH * HW / 4;
    if (i >= n4) return;
    const size_t per = (size_t)C1CH * HW / 4;
    size_t b = i / per, r = i - b * per;
    float4 v = ((const float4*)t1)[i];
    ((float4*)(feat + b * (size_t)FEAT_STRIDE + (size_t)OFF_T1 * HW))[r] = v;
}

// ---------------------------------------------------------------------------
// Bilinear warp of tenTwo by flow*1.25 (zeros padding, align_corners=True)
// flow is read from the feat buffer (channels OFF_FLOW, OFF_FLOW+1)
// ---------------------------------------------------------------------------
__global__ void warp_kernel(const float* __restrict__ tenTwo, const float* __restrict__ feat)
{
    int gid = blockIdx.x * blockDim.x + threadIdx.x;
    if (gid >= Bn * HW) return;
    int b = gid / HW;
    int pix = gid - b * HW;
    int y = pix / W, x = pix - (pix / W) * W;

    const float* fl = feat + (size_t)b * FEAT_STRIDE + (size_t)OFF_FLOW * HW + pix;
    float px = (float)x + fl[0]  * 1.25f;
    float py = (float)y + fl[HW] * 1.25f;
    float fx = floorf(px), fy = floorf(py);
    float wx = px - fx, wy = py - fy;
    int ix0 = (int)fx, iy0 = (int)fy;
    int ix1 = ix0 + 1, iy1 = iy0 + 1;
    bool vx0 = (unsigned)ix0 < W, vx1 = (unsigned)ix1 < W;
    bool vy0 = (unsigned)iy0 < H, vy1 = (unsigned)iy1 < H;
    float w00 = (1.f - wy) * (1.f - wx), w01 = (1.f - wy) * wx;
    float w10 = wy * (1.f - wx),         w11 = wy * wx;
    int o00 = iy0 * W + ix0, o01 = iy0 * W + ix1;
    int o10 = iy1 * W + ix0, o11 = iy1 * W + ix1;

    const float* t = tenTwo + (size_t)b * C1CH * HW;
    float* o = g_warped + (size_t)b * C1CH * HW + pix;
    for (int c = 0; c < C1CH; c++) {
        const float* tc = t + (size_t)c * HW;
        float v = 0.f;
        if (vy0 && vx0) v += tc[o00] * w00;
        if (vy0 && vx1) v += tc[o01] * w01;
        if (vy1 && vx0) v += tc[o10] * w10;
        if (vy1 && vx1) v += tc[o11] * w11;
        o[(size_t)c * HW] = v;
    }
}

// ---------------------------------------------------------------------------
// 81-tap correlation: vol[d] = leaky(mean_c f1[c,y,x] * warped[c, y+dy-4, x+dx-4])
// block = 32x4 pixel tile, 128 threads, 81 accumulators per thread.
// ---------------------------------------------------------------------------
__global__ __launch_bounds__(128) void corr_kernel(const float* __restrict__ tenOne,
                                                   float* __restrict__ feat)
{
    __shared__ float s_f1[4][32];
    __shared__ float s_w2[12][40];
    int tid = threadIdx.x;
    int tx = tid & 31, ty = tid >> 5;
    int x0 = blockIdx.x * 32, y0 = blockIdx.y * 4, b = blockIdx.z;

    float acc[81];
#pragma unroll
    for (int d = 0; d < 81; d++) acc[d] = 0.f;

    const float* f1 = tenOne + (size_t)b * C1CH * HW;
    const float* f2 = g_warped + (size_t)b * C1CH * HW;

    for (int c = 0; c < C1CH; c++) {
        const float* f1c = f1 + (size_t)c * HW;
        const float* f2c = f2 + (size_t)c * HW;
        __syncthreads();
        s_f1[ty][tx] = f1c[(y0 + ty) * W + x0 + tx];
#pragma unroll
        for (int i = 0; i < 4; i++) {
            int idx = tid + i * 128;
            if (idx < 480) {
                int r = idx / 40, cc = idx - (idx / 40) * 40;
                int gy = y0 - 4 + r, gx = x0 - 4 + cc;
                float v = 0.f;
                if ((unsigned)gy < H && (unsigned)gx < W) v = f2c[gy * W + gx];
                s_w2[r][cc] = v;
            }
        }
        __syncthreads();
        float a = s_f1[ty][tx];
#pragma unroll
        for (int dy = 0; dy < 9; dy++)
#pragma unroll
            for (int dx = 0; dx < 9; dx++)
                acc[dy * 9 + dx] += a * s_w2[ty + dy][tx + dx];
    }

    float* o = feat + (size_t)b * FEAT_STRIDE + (size_t)OFF_VOL * HW + (y0 + ty) * W + x0 + tx;
    const float inv = 1.f / 96.f;
#pragma unroll
    for (int d = 0; d < 81; d++) {
        float v = acc[d] * inv;
        o[(size_t)d * HW] = (v >= 0.f) ? v : 0.1f * v;
    }
}

// ---------------------------------------------------------------------------
// Direct 3x3 conv (pad 1), leaky ReLU.
// 256 threads, 64x16 output tile, each thread: 1x4 pixel strip x COUT_BLK couts.
// grid: (coutGroups, 8 tiles, B).  Cout groups fastest -> concurrent blocks
// share input tiles via L2.
// ---------------------------------------------------------------------------
template <int COUT_BLK>
__global__ __launch_bounds__(256) void conv3x3_kernel(
    const float* __restrict__ in,    // batch-0 ptr at input channel offset
    const float* __restrict__ w,     // (CoutTotal, Cin, 3, 3)
    const float* __restrict__ bias,
    float* __restrict__ out,         // batch-0 ptr at output channel offset
    int Cin, int inStride, int outStride)
{
    __shared__ float s_in[18][66];
    __shared__ float s_w[COUT_BLK * 9];
    const int tid = threadIdx.x;
    const int tx = tid & 15, ty = tid >> 4;
    const int g = blockIdx.x;
    const int tileX = blockIdx.y & 1, tileY = blockIdx.y >> 1;
    const int b = blockIdx.z;
    const int x0 = tileX * 64, y0 = tileY * 16;

    const float* inB = in + (size_t)b * inStride;
    float acc[COUT_BLK][4];
#pragma unroll
    for (int c = 0; c < COUT_BLK; c++)
#pragma unroll
        for (int p = 0; p < 4; p++) acc[c][p] = 0.f;

    for (int ci = 0; ci < Cin; ci++) {
        const float* ch = inB + (size_t)ci * HW;
#pragma unroll
        for (int i = 0; i < 5; i++) {
            int idx = tid + i * 256;
            if (idx < 18 * 66) {
                int r = idx / 66, c = idx - (idx / 66) * 66;
                int gy = y0 - 1 + r, gx = x0 - 1 + c;
                float v = 0.f;
                if ((unsigned)gy < H && (unsigned)gx < W) v = ch[gy * W + gx];
                s_in[r][c] = v;
            }
        }
        if (tid < COUT_BLK * 9)
            s_w[tid] = w[((size_t)(g * COUT_BLK + tid / 9) * Cin + ci) * 9 + tid % 9];
        __syncthreads();

        float r0[6], r1[6], r2[6];
#pragma unroll
        for (int k = 0; k < 6; k++) {
            r0[k] = s_in[ty][tx * 4 + k];
            r1[k] = s_in[ty + 1][tx * 4 + k];
            r2[k] = s_in[ty + 2][tx * 4 + k];
        }
#pragma unroll
        for (int co = 0; co < COUT_BLK; co++) {
            float w0 = s_w[co * 9 + 0], w1v = s_w[co * 9 + 1], w2v = s_w[co * 9 + 2];
            float w3v = s_w[co * 9 + 3], w4v = s_w[co * 9 + 4], w5v = s_w[co * 9 + 5];
            float w6v = s_w[co * 9 + 6], w7v = s_w[co * 9 + 7], w8v = s_w[co * 9 + 8];
#pragma unroll
            for (int p = 0; p < 4; p++) {
                float s = acc[co][p];
                s += w0  * r0[p]; s += w1v * r0[p + 1]; s += w2v * r0[p + 2];
                s += w3v * r1[p]; s += w4v * r1[p + 1]; s += w5v * r1[p + 2];
                s += w6v * r2[p]; s += w7v * r2[p + 1]; s += w8v * r2[p + 2];
                acc[co][p] = s;
            }
        }
        __syncthreads();
    }

#pragma unroll
    for (int co = 0; co < COUT_BLK; co++) {
        float bi = bias[g * COUT_BLK + co];
        float* o = out + (size_t)b * outStride + (size_t)(g * COUT_BLK + co) * HW
                 + (y0 + ty) * W + x0 + tx * 4;
#pragma unroll
        for (int p = 0; p < 4; p++) {
            float v = acc[co][p] + bi;
            o[p] = (v >= 0.f) ? v : 0.1f * v;
        }
    }
}

// ---------------------------------------------------------------------------
// Launch
// ---------------------------------------------------------------------------
extern "C" void kernel_launch(void* const* d_in, const int* in_sizes, int n_in,
                              void* d_out, int out_size)
{
    (void)in_sizes; (void)n_in; (void)out_size;
    const float* tenOne    = (const float*)d_in[0];
    const float* tenTwo    = (const float*)d_in[1];
    const float* prev_flow = (const float*)d_in[2];
    const float* prev_feat = (const float*)d_in[3];
    const float* w_upflow  = (const float*)d_in[4];
    const float* b_upflow  = (const float*)d_in[5];
    const float* w_upfeat  = (const float*)d_in[6];
    const float* b_upfeat  = (const float*)d_in[7];
    const float* w1 = (const float*)d_in[8];   const float* b1 = (const float*)d_in[9];
    const float* w2 = (const float*)d_in[10];  const float* b2 = (const float*)d_in[11];
    const float* w3 = (const float*)d_in[12];  const float* b3 = (const float*)d_in[13];
    const float* w4 = (const float*)d_in[14];  const float* b4 = (const float*)d_in[15];
    const float* w5 = (const float*)d_in[16];  const float* b5 = (const float*)d_in[17];
    const float* w6 = (const float*)d_in[18];  const float* b6 = (const float*)d_in[19];

    float* flow = (float*)d_out;                       // (B, 2, H, W)
    float* feat = flow + (size_t)Bn * 2 * HW;          // (B, 629, H, W)

    const int NPIX = Bn * HW;

    // 1. upsample flow -> feat[:, 625:627]
    upconv_kernel<<<(NPIX + 255) / 256, 256>>>(prev_flow, w_upflow, b_upflow,
                                               feat + (size_t)OFF_FLOW * HW, 2);
    // 2. upsample feat -> feat[:, 627:629]
    upconv_kernel<<<(NPIX + 255) / 256, 256>>>(prev_feat, w_upfeat, b_upfeat,
                                               feat + (size_t)OFF_UPF * HW, PREVC);
    // 3. tenOne -> feat[:, 529:625]
    {
        size_t n4 = (size_t)Bn * C1CH * HW / 4;
        copy_t1_kernel<<<(unsigned)((n4 + 255) / 256), 256>>>(tenOne, feat);
    }
    // 4. warp tenTwo with flow*1.25 -> g_warped
    warp_kernel<<<(NPIX + 255) / 256, 256>>>(tenTwo, feat);
    // 5. correlation + leaky -> feat[:, 448:529]
    corr_kernel<<<dim3(W / 32, H / 4, Bn), 128>>>(tenOne, feat);

    // 6. dense conv tower (each writes its slice; inputs are suffixes of feat)
    conv3x3_kernel<8><<<dim3(128 / 8, 8, Bn), 256>>>(
        feat + (size_t)OFF_VOL * HW, w1, b1, feat + (size_t)OFF_C1 * HW,
        181, FEAT_STRIDE, FEAT_STRIDE);
    conv3x3_kernel<8><<<dim3(128 / 8, 8, Bn), 256>>>(
        feat + (size_t)OFF_C1 * HW, w2, b2, feat + (size_t)OFF_C2 * HW,
        309, FEAT_STRIDE, FEAT_STRIDE);
    conv3x3_kernel<8><<<dim3(96 / 8, 8, Bn), 256>>>(
        feat + (size_t)OFF_C2 * HW, w3, b3, feat + (size_t)OFF_C3 * HW,
        437, FEAT_STRIDE, FEAT_STRIDE);
    conv3x3_kernel<8><<<dim3(64 / 8, 8, Bn), 256>>>(
        feat + (size_t)OFF_C3 * HW, w4, b4, feat + (size_t)OFF_C4 * HW,
        533, FEAT_STRIDE, FEAT_STRIDE);
    conv3x3_kernel<8><<<dim3(32 / 8, 8, Bn), 256>>>(
        feat + (size_t)OFF_C4 * HW, w5, b5, feat + (size_t)OFF_C5 * HW,
        597, FEAT_STRIDE, FEAT_STRIDE);
    // conv6 -> flow output (Cout = 2)
    conv3x3_kernel<2><<<dim3(1, 8, Bn), 256>>>(
        feat + (size_t)OFF_C5 * HW, w6, b6, flow,
        629, FEAT_STRIDE, 2 * HW);
}